// round 11
// baseline (speedup 1.0000x reference)
#include <cuda_runtime.h>

// LocalVariation: out[b, k, y, x] = x[b,y,x] - xp[b, y+i, x+j]  (replicate pad, 5x5, skip center)
// Input : [16, 1, 512, 512] f32
// Output: [16, 24, 512, 512] f32
//
// Tile: 512 (x, full row) by 2 (y), blockDim (128,2)=256 threads.
// Each thread computes 4 consecutive x pixels -> float4 streaming stores, 24 channels.
//
// Wave-quantization fix: 4096 tiles; smem padded to 30.7KB caps residency at
// 7 blocks/SM -> 1036 concurrent -> 4096/1036 = 3.95 waves (98.8% full last
// wave) instead of the previous 3.46->4 waves (86.5% utilization).

#define KSZ   5
#define PAD   2
#define H     512
#define W     512
#define B     16
#define NCH   24
#define TILE_X 512
#define TILE_Y 2
#define SM_W  (TILE_X + 2 * PAD)   // 516 valid cols
#define SM_STRIDE 1280             // padded: 6*1280*4 = 30720B -> 7 blocks/SM cap
#define SM_H  (TILE_Y + 2 * PAD)   // 6 rows
#define SM_ELEMS (SM_H * SM_W)     // 3096

__global__ __launch_bounds__(256, 7)
void localvar_kernel(const float* __restrict__ in, float* __restrict__ out) {
    __shared__ float sm[SM_H * SM_STRIDE];   // 30720 B static

    const int b   = blockIdx.y;
    const int by0 = blockIdx.x * TILE_Y;

    const int tid = threadIdx.y * 128 + threadIdx.x;
    const float* inb = in + b * (H * W);

    // ---- fill smem tile with replicate-clamped input ----
    // 3096 elements / 256 threads -> fixed 13 iterations, fully unrolled (MLP).
    #pragma unroll
    for (int it = 0; it < 13; it++) {
        int idx = tid + it * 256;
        if (idx < SM_ELEMS) {
            int r = idx / SM_W;
            int c = idx - r * SM_W;
            int gy = by0 + r - PAD;
            int gx = c - PAD;                 // tile spans full row
            gy = gy < 0 ? 0 : (gy > H - 1 ? H - 1 : gy);
            gx = gx < 0 ? 0 : (gx > W - 1 ? W - 1 : gx);
            sm[r * SM_STRIDE + c] = inb[gy * W + gx];
        }
    }
    __syncthreads();

    // ---- compute ----
    const int tx = threadIdx.x;       // 0..127
    const int ty = threadIdx.y;       // 0..1
    const int px = tx * 4;            // local x of first of 4 pixels (0..508)

    // Center pixels: sm[ty+PAD][px+PAD .. px+PAD+3], 8B-aligned -> two LDS.64
    const float2 cA = *(const float2*)&sm[(ty + PAD) * SM_STRIDE + px + 2];
    const float2 cB = *(const float2*)&sm[(ty + PAD) * SM_STRIDE + px + 4];
    const float c0 = cA.x, c1 = cA.y, c2 = cB.x, c3 = cB.y;

    const int gy = by0 + ty;
    float* outp = out + ((long long)b * NCH * H + gy) * W + px;

    int k = 0;
    #pragma unroll
    for (int i = 0; i < KSZ; i++) {
        // Load this row's 8 floats (16B-aligned pair of LDS.128)
        const float4* p = (const float4*)&sm[(ty + i) * SM_STRIDE + px];
        float4 a = p[0];
        float4 d = p[1];
        float rr[8] = {a.x, a.y, a.z, a.w, d.x, d.y, d.z, d.w};

        #pragma unroll
        for (int j = 0; j < KSZ; j++) {
            if (i == PAD && j == PAD) continue;
            float4 v;
            v.x = c0 - rr[j + 0];
            v.y = c1 - rr[j + 1];
            v.z = c2 - rr[j + 2];
            v.w = c3 - rr[j + 3];
            __stcs((float4*)(outp + (long long)k * (H * W)), v);
            k++;
        }
    }
}

extern "C" void kernel_launch(void* const* d_in, const int* in_sizes, int n_in,
                              void* d_out, int out_size) {
    const float* x = (const float*)d_in[0];
    float* out = (float*)d_out;
    dim3 block(128, 2, 1);
    dim3 grid(H / TILE_Y, B, 1);    // 256 x 16 = 4096 blocks
    localvar_kernel<<<grid, block>>>(x, out);
}

// round 13
// speedup vs baseline: 1.3891x; 1.3891x over previous
#include <cuda_runtime.h>

// LocalVariation: out[b, k, y, x] = x[b,y,x] - xp[b, y+i, x+j]  (replicate pad, 5x5, skip center)
// Input : [16, 1, 512, 512] f32
// Output: [16, 24, 512, 512] f32
//
// Tile: 512 (x, full row) by 4 (y), blockDim (128,4)=512 threads (R10 config).
// Channel-split: blockIdx.z in {0,1} selects channels [0,12) or [12,24).
// Grid 4096 blocks / 592 concurrent = 6.92 -> 7 waves at 98.9% utilization
// (vs 3.46 -> 4 waves, 86.5%, without the split).

#define KSZ   5
#define PAD   2
#define H     512
#define W     512
#define B     16
#define NCH   24
#define TILE_X 512
#define TILE_Y 4
#define SM_W  (TILE_X + 2 * PAD)   // 516 valid cols
#define SM_STRIDE 520              // 16B-aligned row stride (520*4 = 2080 B)
#define SM_H  (TILE_Y + 2 * PAD)   // 8 rows
#define SM_ELEMS (SM_H * SM_W)     // 4128

template<int KBEG, int KEND>
__device__ __forceinline__ void compute_channels(
    const float* __restrict__ sm, int ty, int px,
    float c0, float c1, float c2, float c3, float* __restrict__ outp)
{
    int k = 0;
    #pragma unroll
    for (int i = 0; i < KSZ; i++) {
        // Row loads are DCE'd for rows with no channels in [KBEG, KEND).
        const float4* p = (const float4*)&sm[(ty + i) * SM_STRIDE + px];
        float4 a = p[0];
        float4 d = p[1];
        float rr[8] = {a.x, a.y, a.z, a.w, d.x, d.y, d.z, d.w};

        #pragma unroll
        for (int j = 0; j < KSZ; j++) {
            if (i == PAD && j == PAD) continue;
            if (k >= KBEG && k < KEND) {
                float4 v;
                v.x = c0 - rr[j + 0];
                v.y = c1 - rr[j + 1];
                v.z = c2 - rr[j + 2];
                v.w = c3 - rr[j + 3];
                __stcs((float4*)(outp + (long long)k * (H * W)), v);
            }
            k++;
        }
    }
}

__global__ __launch_bounds__(512, 4)
void localvar_kernel(const float* __restrict__ in, float* __restrict__ out) {
    __shared__ float sm[SM_H * SM_STRIDE];   // 16640 B

    const int b   = blockIdx.y;
    const int by0 = blockIdx.x * TILE_Y;

    const int tid = threadIdx.y * 128 + threadIdx.x;
    const float* inb = in + b * (H * W);

    // ---- fill smem tile with replicate-clamped input (R10-identical) ----
    #pragma unroll
    for (int it = 0; it < 9; it++) {
        int idx = tid + it * 512;
        if (idx < SM_ELEMS) {
            int r = idx / SM_W;
            int c = idx - r * SM_W;
            int gy = by0 + r - PAD;
            int gx = c - PAD;                 // tile spans full row
            gy = gy < 0 ? 0 : (gy > H - 1 ? H - 1 : gy);
            gx = gx < 0 ? 0 : (gx > W - 1 ? W - 1 : gx);
            sm[r * SM_STRIDE + c] = inb[gy * W + gx];
        }
    }
    __syncthreads();

    // ---- compute ----
    const int tx = threadIdx.x;       // 0..127
    const int ty = threadIdx.y;       // 0..3
    const int px = tx * 4;            // local x of first of 4 pixels (0..508)

    const float2 cA = *(const float2*)&sm[(ty + PAD) * SM_STRIDE + px + 2];
    const float2 cB = *(const float2*)&sm[(ty + PAD) * SM_STRIDE + px + 4];
    const float c0 = cA.x, c1 = cA.y, c2 = cB.x, c3 = cB.y;

    const int gy = by0 + ty;
    float* outp = out + ((long long)b * NCH * H + gy) * W + px;

    if (blockIdx.z == 0)
        compute_channels<0, 12>(sm, ty, px, c0, c1, c2, c3, outp);
    else
        compute_channels<12, 24>(sm, ty, px, c0, c1, c2, c3, outp);
}

extern "C" void kernel_launch(void* const* d_in, const int* in_sizes, int n_in,
                              void* d_out, int out_size) {
    const float* x = (const float*)d_in[0];
    float* out = (float*)d_out;
    dim3 block(128, 4, 1);
    dim3 grid(H / TILE_Y, B, 2);    // 128 x 16 x 2 = 4096 blocks
    localvar_kernel<<<grid, block>>>(x, out);
}

// round 14
// speedup vs baseline: 1.5725x; 1.1321x over previous
#include <cuda_runtime.h>

// LocalVariation: out[b, k, y, x] = x[b,y,x] - xp[b, y+i, x+j]  (replicate pad, 5x5, skip center)
// Input : [16, 1, 512, 512] f32
// Output: [16, 24, 512, 512] f32
//
// Tile: 256 (x) by 4 (y), blockDim (128,4)=512 threads, 2 px/thread (float2 stores).
// 4096 blocks / (148 SMs x 4 resident) = 6.92 -> 7 waves, 98.9% utilization
// (vs 3.46 -> 4 waves = 86.5% at 4 px/thread). Tile filled once; halo amp 2.03x.

#define KSZ   5
#define PAD   2
#define H     512
#define W     512
#define B     16
#define NCH   24
#define TILE_X 256
#define TILE_Y 4
#define NTX   (W / TILE_X)         // 2 x-tiles
#define SM_W  (TILE_X + 2 * PAD)   // 260 valid cols
#define SM_STRIDE 264              // 8B-aligned-friendly row stride
#define SM_H  (TILE_Y + 2 * PAD)   // 8 rows
#define SM_ELEMS (SM_H * SM_W)     // 2080

__global__ __launch_bounds__(512, 4)
void localvar_kernel(const float* __restrict__ in, float* __restrict__ out) {
    __shared__ float sm[SM_H * SM_STRIDE];   // 8448 B

    const int bxt = blockIdx.x & (NTX - 1);        // x-tile 0..1
    const int byt = blockIdx.x >> 1;               // y-tile 0..127
    const int b   = blockIdx.y;
    const int by0 = byt * TILE_Y;
    const int bx0 = bxt * TILE_X;

    const int tid = threadIdx.y * 128 + threadIdx.x;
    const float* inb = in + b * (H * W);

    // ---- fill smem tile with replicate-clamped input ----
    // 2080 elements / 512 threads -> fixed 5 iterations, fully unrolled (MLP).
    #pragma unroll
    for (int it = 0; it < 5; it++) {
        int idx = tid + it * 512;
        if (idx < SM_ELEMS) {
            int r = idx / SM_W;
            int c = idx - r * SM_W;
            int gy = by0 + r - PAD;
            int gx = bx0 + c - PAD;
            gy = gy < 0 ? 0 : (gy > H - 1 ? H - 1 : gy);
            gx = gx < 0 ? 0 : (gx > W - 1 ? W - 1 : gx);
            sm[r * SM_STRIDE + c] = inb[gy * W + gx];
        }
    }
    __syncthreads();

    // ---- compute: 2 consecutive x pixels per thread ----
    const int tx = threadIdx.x;       // 0..127
    const int ty = threadIdx.y;       // 0..3
    const int px = tx * 2;            // local x of first of 2 pixels (even)

    // Center pixels: sm[ty+PAD][px+PAD], sm[ty+PAD][px+PAD+1]
    const float2 cC = *(const float2*)&sm[(ty + PAD) * SM_STRIDE + px + 2];
    const float c0 = cC.x, c1 = cC.y;

    const int gy = by0 + ty;
    float* outp = out + ((long long)b * NCH * H + gy) * W + bx0 + px;

    int k = 0;
    #pragma unroll
    for (int i = 0; i < KSZ; i++) {
        // This row needs sm[ty+i][px .. px+5]: three aligned LDS.64
        const float* rowp = &sm[(ty + i) * SM_STRIDE + px];
        float2 a = *(const float2*)(rowp + 0);
        float2 d = *(const float2*)(rowp + 2);
        float2 e = *(const float2*)(rowp + 4);
        float rr[6] = {a.x, a.y, d.x, d.y, e.x, e.y};

        #pragma unroll
        for (int j = 0; j < KSZ; j++) {
            if (i == PAD && j == PAD) continue;
            float2 v;
            v.x = c0 - rr[j + 0];
            v.y = c1 - rr[j + 1];
            __stcs((float2*)(outp + (long long)k * (H * W)), v);
            k++;
        }
    }
}

extern "C" void kernel_launch(void* const* d_in, const int* in_sizes, int n_in,
                              void* d_out, int out_size) {
    const float* x = (const float*)d_in[0];
    float* out = (float*)d_out;
    dim3 block(128, 4, 1);
    dim3 grid(NTX * (H / TILE_Y), B, 1);   // 256 x 16 = 4096 blocks
    localvar_kernel<<<grid, block>>>(x, out);
}